// round 1
// baseline (speedup 1.0000x reference)
#include <cuda_runtime.h>
#include <math.h>

#define B    32
#define C    3
#define H    512
#define W    512
#define TILE 32
#define HALO 3
#define SMW  (TILE + 2*HALO)   // 38
#define SMP  40                // padded smem row stride (avoid conflicts)
#define TILES_PER_IMG 256      // (512/32)^2

// Scratch: per-block partials (deterministic two-stage reduction, no atomics)
__device__ float g_psum [B * TILES_PER_IMG];
__device__ float g_psumsq[B * TILES_PER_IMG];
__device__ float g_pS   [B * TILES_PER_IMG];

__device__ __forceinline__ int refl(int i) {
    // reflect (no edge repeat), pad <= 3 so single reflection suffices
    i = abs(i);
    return (i >= H) ? (2 * H - 2 - i) : i;
}

__global__ __launch_bounds__(256, 4)
void ldl_main(const float* __restrict__ net, const float* __restrict__ gt) {
    __shared__ float res[SMW][SMP];
    __shared__ float h1 [SMW][TILE];
    __shared__ float h2 [SMW][TILE];
    __shared__ float red[3][8];

    const int b   = blockIdx.z;
    const int x0  = blockIdx.x * TILE - HALO;
    const int y0  = blockIdx.y * TILE - HALO;
    const int tid = threadIdx.x;

    const long HW   = (long)H * W;
    const float* netb = net + (long)b * C * HW;
    const float* gtb  = gt  + (long)b * C * HW;

    // ---- residual tile (with halo), reflect-indexed, fused from 6 planes ----
    for (int i = tid; i < SMW * SMW; i += 256) {
        int ly = i / SMW, lx = i - ly * SMW;
        int gy = refl(y0 + ly);
        int gx = refl(x0 + lx);
        long p = (long)gy * W + gx;
        float r = fabsf(gtb[p]        - netb[p])
                + fabsf(gtb[p + HW]   - netb[p + HW])
                + fabsf(gtb[p + 2*HW] - netb[p + 2*HW]);
        res[ly][lx] = r;
    }
    __syncthreads();

    // ---- horizontal 7-wide sums of r and r^2 ----
    for (int i = tid; i < SMW * TILE; i += 256) {
        int ly = i >> 5, ox = i & 31;
        float s1 = 0.f, s2 = 0.f;
        #pragma unroll
        for (int d = 0; d < 7; d++) {
            float v = res[ly][ox + d];
            s1 += v;
            s2 += v * v;
        }
        h1[ly][ox] = s1;
        h2[ly][ox] = s2;
    }
    __syncthreads();

    // ---- vertical 7-wide sums -> pixel_w; accumulate loss + patch stats ----
    const int tx = tid & 31, ty = tid >> 5;
    float accS = 0.f, accSum = 0.f, accSq = 0.f;
    #pragma unroll
    for (int r = 0; r < 4; r++) {
        int oy = ty + r * 8;
        float s1 = 0.f, s2 = 0.f;
        #pragma unroll
        for (int d = 0; d < 7; d++) {
            s1 += h1[oy + d][tx];
            s2 += h2[oy + d][tx];
        }
        float pw  = (s2 - s1 * s1 * (1.0f / 49.0f)) * (1.0f / 48.0f);
        float cen = res[oy + HALO][tx + HALO];
        accS   += fabsf(pw) * cen;
        accSum += cen;
        accSq  += cen * cen;
    }

    // ---- deterministic block reduction ----
    #pragma unroll
    for (int off = 16; off; off >>= 1) {
        accS   += __shfl_down_sync(0xFFFFFFFFu, accS,   off);
        accSum += __shfl_down_sync(0xFFFFFFFFu, accSum, off);
        accSq  += __shfl_down_sync(0xFFFFFFFFu, accSq,  off);
    }
    if (tx == 0) { red[0][ty] = accS; red[1][ty] = accSum; red[2][ty] = accSq; }
    __syncthreads();
    if (tid == 0) {
        float S = 0.f, Su = 0.f, Sq = 0.f;
        #pragma unroll
        for (int w = 0; w < 8; w++) { S += red[0][w]; Su += red[1][w]; Sq += red[2][w]; }
        int tile = blockIdx.y * gridDim.x + blockIdx.x;
        g_pS    [b * TILES_PER_IMG + tile] = S;
        g_psum  [b * TILES_PER_IMG + tile] = Su;
        g_psumsq[b * TILES_PER_IMG + tile] = Sq;
    }
}

__device__ __forceinline__ double blk_reduce256(double v, double* sh, int tid) {
    sh[tid] = v;
    __syncthreads();
    #pragma unroll
    for (int s = 128; s; s >>= 1) {
        if (tid < s) sh[tid] += sh[tid + s];
        __syncthreads();
    }
    double r = sh[0];
    __syncthreads();
    return r;
}

__global__ __launch_bounds__(256)
void ldl_final(float* __restrict__ out) {
    __shared__ double sh[256];
    const int tid = threadIdx.x;
    double total = 0.0;

    for (int b = 0; b < B; b++) {
        double su = (double)g_psum  [b * TILES_PER_IMG + tid];
        double sq = (double)g_psumsq[b * TILES_PER_IMG + tid];
        double S  = (double)g_pS    [b * TILES_PER_IMG + tid];

        double sumr  = blk_reduce256(su, sh, tid);
        double sumsq = blk_reduce256(sq, sh, tid);
        double Sb    = blk_reduce256(S,  sh, tid);

        if (tid == 0) {
            const double N = (double)(H * W);
            double var = (sumsq - sumr * sumr / N) / (N - 1.0);
            if (var < 0.0) var = 0.0;
            double pw = pow(var, 0.2);
            total += pw * Sb;
        }
    }
    if (tid == 0) {
        out[0] = (float)(total / ((double)B * C * H * W));
    }
}

extern "C" void kernel_launch(void* const* d_in, const int* in_sizes, int n_in,
                              void* d_out, int out_size) {
    const float* net = (const float*)d_in[0];   // net_output
    const float* gt  = (const float*)d_in[1];   // gt
    float* out = (float*)d_out;

    dim3 grid(W / TILE, H / TILE, B);           // 16 x 16 x 32
    ldl_main<<<grid, 256>>>(net, gt);
    ldl_final<<<1, 256>>>(out);
}

// round 2
// speedup vs baseline: 3.2696x; 3.2696x over previous
#include <cuda_runtime.h>
#include <math.h>

#define B    32
#define C    3
#define H    512
#define W    512
#define TILE 32
#define HALO 3
#define SMW  (TILE + 2*HALO)   // 38
#define SMP  40                // padded smem row stride (avoid conflicts)
#define TILES_PER_IMG 256      // (512/32)^2

// Scratch: per-block partials (deterministic two-stage reduction, no atomics)
__device__ float g_psum [B * TILES_PER_IMG];
__device__ float g_psumsq[B * TILES_PER_IMG];
__device__ float g_pS   [B * TILES_PER_IMG];
__device__ double g_batch[B];

__device__ __forceinline__ int refl(int i) {
    // reflect (no edge repeat), pad <= 3 so single reflection suffices
    i = abs(i);
    return (i >= H) ? (2 * H - 2 - i) : i;
}

__global__ __launch_bounds__(256, 4)
void ldl_main(const float* __restrict__ net, const float* __restrict__ gt) {
    __shared__ float res[SMW][SMP];
    __shared__ float h1 [SMW][TILE];
    __shared__ float h2 [SMW][TILE];
    __shared__ float red[3][8];

    const int b   = blockIdx.z;
    const int x0  = blockIdx.x * TILE - HALO;
    const int y0  = blockIdx.y * TILE - HALO;
    const int tid = threadIdx.x;

    const long HW   = (long)H * W;
    const float* netb = net + (long)b * C * HW;
    const float* gtb  = gt  + (long)b * C * HW;

    // ---- residual tile (with halo), reflect-indexed, fused from 6 planes ----
    for (int i = tid; i < SMW * SMW; i += 256) {
        int ly = i / SMW, lx = i - ly * SMW;
        int gy = refl(y0 + ly);
        int gx = refl(x0 + lx);
        long p = (long)gy * W + gx;
        float r = fabsf(gtb[p]        - netb[p])
                + fabsf(gtb[p + HW]   - netb[p + HW])
                + fabsf(gtb[p + 2*HW] - netb[p + 2*HW]);
        res[ly][lx] = r;
    }
    __syncthreads();

    // ---- horizontal 7-wide sums of r and r^2 ----
    for (int i = tid; i < SMW * TILE; i += 256) {
        int ly = i >> 5, ox = i & 31;
        float s1 = 0.f, s2 = 0.f;
        #pragma unroll
        for (int d = 0; d < 7; d++) {
            float v = res[ly][ox + d];
            s1 += v;
            s2 += v * v;
        }
        h1[ly][ox] = s1;
        h2[ly][ox] = s2;
    }
    __syncthreads();

    // ---- vertical 7-wide sums -> pixel_w; accumulate loss + patch stats ----
    const int tx = tid & 31, ty = tid >> 5;
    float accS = 0.f, accSum = 0.f, accSq = 0.f;
    #pragma unroll
    for (int r = 0; r < 4; r++) {
        int oy = ty + r * 8;
        float s1 = 0.f, s2 = 0.f;
        #pragma unroll
        for (int d = 0; d < 7; d++) {
            s1 += h1[oy + d][tx];
            s2 += h2[oy + d][tx];
        }
        float pw  = (s2 - s1 * s1 * (1.0f / 49.0f)) * (1.0f / 48.0f);
        float cen = res[oy + HALO][tx + HALO];
        accS   += fabsf(pw) * cen;
        accSum += cen;
        accSq  += cen * cen;
    }

    // ---- deterministic block reduction ----
    #pragma unroll
    for (int off = 16; off; off >>= 1) {
        accS   += __shfl_down_sync(0xFFFFFFFFu, accS,   off);
        accSum += __shfl_down_sync(0xFFFFFFFFu, accSum, off);
        accSq  += __shfl_down_sync(0xFFFFFFFFu, accSq,  off);
    }
    if (tx == 0) { red[0][ty] = accS; red[1][ty] = accSum; red[2][ty] = accSq; }
    __syncthreads();
    if (tid == 0) {
        float S = 0.f, Su = 0.f, Sq = 0.f;
        #pragma unroll
        for (int w = 0; w < 8; w++) { S += red[0][w]; Su += red[1][w]; Sq += red[2][w]; }
        int tile = blockIdx.y * gridDim.x + blockIdx.x;
        g_pS    [b * TILES_PER_IMG + tile] = S;
        g_psum  [b * TILES_PER_IMG + tile] = Su;
        g_psumsq[b * TILES_PER_IMG + tile] = Sq;
    }
}

// One block per batch: reduce 256 partials (3 streams) + compute pow, in parallel.
__global__ __launch_bounds__(256)
void ldl_batch() {
    __shared__ double shS[8], shU[8], shQ[8];
    const int b   = blockIdx.x;
    const int tid = threadIdx.x;
    const int lane = tid & 31, wrp = tid >> 5;

    double S  = (double)g_pS    [b * TILES_PER_IMG + tid];
    double su = (double)g_psum  [b * TILES_PER_IMG + tid];
    double sq = (double)g_psumsq[b * TILES_PER_IMG + tid];

    #pragma unroll
    for (int off = 16; off; off >>= 1) {
        S  += __shfl_down_sync(0xFFFFFFFFu, S,  off);
        su += __shfl_down_sync(0xFFFFFFFFu, su, off);
        sq += __shfl_down_sync(0xFFFFFFFFu, sq, off);
    }
    if (lane == 0) { shS[wrp] = S; shU[wrp] = su; shQ[wrp] = sq; }
    __syncthreads();
    if (tid == 0) {
        double Sb = 0.0, sumr = 0.0, sumsq = 0.0;
        #pragma unroll
        for (int w = 0; w < 8; w++) { Sb += shS[w]; sumr += shU[w]; sumsq += shQ[w]; }
        const double N = (double)(H * W);
        double var = (sumsq - sumr * sumr / N) / (N - 1.0);
        if (var < 0.0) var = 0.0;
        g_batch[b] = pow(var, 0.2) * Sb;
    }
}

__global__ __launch_bounds__(32)
void ldl_out(float* __restrict__ out) {
    const int tid = threadIdx.x;
    double v = g_batch[tid];
    #pragma unroll
    for (int off = 16; off; off >>= 1)
        v += __shfl_down_sync(0xFFFFFFFFu, v, off);
    if (tid == 0)
        out[0] = (float)(v / ((double)B * C * H * W));
}

extern "C" void kernel_launch(void* const* d_in, const int* in_sizes, int n_in,
                              void* d_out, int out_size) {
    const float* net = (const float*)d_in[0];   // net_output
    const float* gt  = (const float*)d_in[1];   // gt
    float* out = (float*)d_out;

    dim3 grid(W / TILE, H / TILE, B);           // 16 x 16 x 32
    ldl_main<<<grid, 256>>>(net, gt);
    ldl_batch<<<B, 256>>>();
    ldl_out<<<1, 32>>>(out);
}

// round 5
// speedup vs baseline: 5.0177x; 1.5347x over previous
#include <cuda_runtime.h>
#include <math.h>

#define B    32
#define C    3
#define H    512
#define W    512
#define TX   64               // output tile width
#define TY   32               // output tile height
#define HALO 3
#define RW   72               // res smem row width (aligned load span)
#define RH   38               // res smem rows (TY + 6)
#define TILES_PER_IMG 128     // (512/64)*(512/32)

__device__ float g_psum  [B * TILES_PER_IMG];
__device__ float g_psumsq[B * TILES_PER_IMG];
__device__ float g_pS    [B * TILES_PER_IMG];
__device__ double g_batch[B];

__global__ __launch_bounds__(256, 6)
void ldl_main(const float* __restrict__ net, const float* __restrict__ gt) {
    __shared__ float res[RH][RW];      // residual, col c <-> gx = 64*bx-4+c
    __shared__ float h1 [RH][TX];      // horizontal 7-sums of r
    __shared__ float h2 [RH][TX];      // horizontal 7-sums of r^2
    __shared__ float red[3][8];

    const int bx  = blockIdx.x;        // 0..7
    const int by  = blockIdx.y;        // 0..15
    const int b   = blockIdx.z;
    const int tid = threadIdx.x;

    const int x0a = TX * bx - 4;       // global x of smem col 0 (16B aligned)
    const int y0a = TY * by - 3;       // global y of smem row 0

    const int HW = H * W;
    const float* nb = net + b * (C * HW);
    const float* gb = gt  + b * (C * HW);

    // ---- Phase 1: vectorized residual load (skip out-of-range vec4s) ----
    // 38 rows x 18 float4 = 684 tasks
    for (int i = tid; i < RH * 18; i += 256) {
        int row = i / 18, v = i - row * 18;
        int gy = y0a + row;
        int gx = x0a + 4 * v;          // multiple of 4 -> vec4 fully in or out
        if ((unsigned)gy < H && (unsigned)gx < W) {
            int p = gy * W + gx;       // element offset, fits 32-bit
            float4 n0 = *(const float4*)(nb + p);
            float4 n1 = *(const float4*)(nb + p + HW);
            float4 n2 = *(const float4*)(nb + p + 2 * HW);
            float4 g0 = *(const float4*)(gb + p);
            float4 g1 = *(const float4*)(gb + p + HW);
            float4 g2 = *(const float4*)(gb + p + 2 * HW);
            float4 r;
            r.x = fabsf(g0.x - n0.x) + fabsf(g1.x - n1.x) + fabsf(g2.x - n2.x);
            r.y = fabsf(g0.y - n0.y) + fabsf(g1.y - n1.y) + fabsf(g2.y - n2.y);
            r.z = fabsf(g0.z - n0.z) + fabsf(g1.z - n1.z) + fabsf(g2.z - n2.z);
            r.w = fabsf(g0.w - n0.w) + fabsf(g1.w - n1.w) + fabsf(g2.w - n2.w);
            *(float4*)&res[row][4 * v] = r;
        }
    }
    __syncthreads();

    // ---- Phase 1b: reflect fixups (sources are always inside the tile) ----
    if (by == 0) {                     // rows 0,1,2 <- rows 6,5,4  (gy=-3..-1 -> 3..1)
        for (int i = tid; i < 3 * 18; i += 256) {
            int r = i / 18, v = i - r * 18;
            *(float4*)&res[r][4 * v] = *(const float4*)&res[6 - r][4 * v];
        }
    }
    if (by == 15) {                    // rows 35,36,37 <- rows 33,32,31 (gy=512.. -> 510..)
        for (int i = tid; i < 3 * 18; i += 256) {
            int r = 35 + i / 18, v = i % 18;
            *(float4*)&res[r][4 * v] = *(const float4*)&res[68 - r][4 * v];
        }
    }
    __syncthreads();
    if (bx == 0) {                     // cols 1,2,3 <- cols 7,6,5   (gx=-3..-1 -> 3..1)
        for (int i = tid; i < RH * 3; i += 256) {
            int r = i / 3, c = 1 + i % 3;
            res[r][c] = res[r][8 - c];
        }
    }
    if (bx == 7) {                     // cols 68,69,70 <- cols 66,65,64 (gx=512.. -> 510..)
        for (int i = tid; i < RH * 3; i += 256) {
            int r = i / 3, c = 68 + i % 3;
            res[r][c] = res[r][134 - c];   // gx' = 1022 - gx  =>  c' = 134 - c
        }
    }
    __syncthreads();

    // ---- Phase 2: horizontal 7-tap (conflict-free, one read per tap) ----
    for (int i = tid; i < RH * TX; i += 256) {
        int row = i >> 6, ox = i & 63;
        float s1 = 0.f, s2 = 0.f;
        #pragma unroll
        for (int d = 0; d < 7; d++) {
            float v = res[row][1 + ox + d];
            s1 += v;
            s2 += v * v;
        }
        h1[row][ox] = s1;
        h2[row][ox] = s2;
    }
    __syncthreads();

    // ---- Phase 3: vertical sliding 7-sum, 8 outputs per thread ----
    const int tx  = tid & 63;          // column 0..63
    const int grp = tid >> 6;          // 0..3 -> rows grp*8 .. grp*8+7
    const int ybase = grp * 8;

    float s1 = 0.f, s2 = 0.f;
    #pragma unroll
    for (int d = 0; d < 7; d++) {
        s1 += h1[ybase + d][tx];
        s2 += h2[ybase + d][tx];
    }
    float accS = 0.f, accSum = 0.f, accSq = 0.f;
    #pragma unroll
    for (int j = 0; j < 8; j++) {
        float pw  = (s2 - s1 * s1 * (1.0f / 49.0f)) * (1.0f / 48.0f);
        float cen = res[ybase + j + 3][tx + 4];
        accS   += fabsf(pw) * cen;
        accSum += cen;
        accSq  += cen * cen;
        if (j < 7) {
            s1 += h1[ybase + j + 7][tx] - h1[ybase + j][tx];
            s2 += h2[ybase + j + 7][tx] - h2[ybase + j][tx];
        }
    }

    // ---- block reduction ----
    #pragma unroll
    for (int off = 16; off; off >>= 1) {
        accS   += __shfl_down_sync(0xFFFFFFFFu, accS,   off);
        accSum += __shfl_down_sync(0xFFFFFFFFu, accSum, off);
        accSq  += __shfl_down_sync(0xFFFFFFFFu, accSq,  off);
    }
    const int lane = tid & 31, wrp = tid >> 5;
    if (lane == 0) { red[0][wrp] = accS; red[1][wrp] = accSum; red[2][wrp] = accSq; }
    __syncthreads();
    if (tid == 0) {
        float S = 0.f, Su = 0.f, Sq = 0.f;
        #pragma unroll
        for (int w = 0; w < 8; w++) { S += red[0][w]; Su += red[1][w]; Sq += red[2][w]; }
        int tile = by * 8 + bx;
        g_pS    [b * TILES_PER_IMG + tile] = S;
        g_psum  [b * TILES_PER_IMG + tile] = Su;
        g_psumsq[b * TILES_PER_IMG + tile] = Sq;
    }
}

// One block per batch: reduce 128 partials + pow, all batches in parallel.
__global__ __launch_bounds__(128)
void ldl_batch() {
    __shared__ double shS[4], shU[4], shQ[4];
    const int b   = blockIdx.x;
    const int tid = threadIdx.x;
    const int lane = tid & 31, wrp = tid >> 5;

    double S  = (double)g_pS    [b * TILES_PER_IMG + tid];
    double su = (double)g_psum  [b * TILES_PER_IMG + tid];
    double sq = (double)g_psumsq[b * TILES_PER_IMG + tid];

    #pragma unroll
    for (int off = 16; off; off >>= 1) {
        S  += __shfl_down_sync(0xFFFFFFFFu, S,  off);
        su += __shfl_down_sync(0xFFFFFFFFu, su, off);
        sq += __shfl_down_sync(0xFFFFFFFFu, sq, off);
    }
    if (lane == 0) { shS[wrp] = S; shU[wrp] = su; shQ[wrp] = sq; }
    __syncthreads();
    if (tid == 0) {
        double Sb = 0.0, sumr = 0.0, sumsq = 0.0;
        #pragma unroll
        for (int w = 0; w < 4; w++) { Sb += shS[w]; sumr += shU[w]; sumsq += shQ[w]; }
        const double N = (double)(H * W);
        double var = (sumsq - sumr * sumr / N) / (N - 1.0);
        if (var < 0.0) var = 0.0;
        g_batch[b] = pow(var, 0.2) * Sb;
    }
}

__global__ __launch_bounds__(32)
void ldl_out(float* __restrict__ out) {
    const int tid = threadIdx.x;
    double v = g_batch[tid];
    #pragma unroll
    for (int off = 16; off; off >>= 1)
        v += __shfl_down_sync(0xFFFFFFFFu, v, off);
    if (tid == 0)
        out[0] = (float)(v / ((double)B * C * H * W));
}

extern "C" void kernel_launch(void* const* d_in, const int* in_sizes, int n_in,
                              void* d_out, int out_size) {
    const float* net = (const float*)d_in[0];   // net_output
    const float* gt  = (const float*)d_in[1];   // gt
    float* out = (float*)d_out;

    dim3 grid(W / TX, H / TY, B);               // 8 x 16 x 32
    ldl_main<<<grid, 256>>>(net, gt);
    ldl_batch<<<B, 128>>>();
    ldl_out<<<1, 32>>>(out);
}